// round 10
// baseline (speedup 1.0000x reference)
#include <cuda_runtime.h>
#include <cuda_bf16.h>
#include <cstdint>

// Problem constants
#define BB    2
#define TT    2048
#define DD    1024
#define HH    16
#define DH    64
#define BT    (BB*TT)          // 4096
#define NELE  ((size_t)BT*DD)  // 4,194,304

// ---------------------------------------------------------------------------
// Scratch (no cudaMalloc allowed -> __device__ globals)
// ---------------------------------------------------------------------------
__device__ float g_qpre[NELE];
__device__ float g_kpre[NELE];
__device__ float g_vpre[NELE];
__device__ float g_gpre[NELE];
__device__ float g_qn[NELE];
__device__ float g_kn[NELE];
__device__ float g_vn[NELE];
__device__ float g_o[NELE];
__device__ float g_og[NELE];
__device__ float g_beta[BT*HH];

// ---------------------------------------------------------------------------
// Packed f32x2 helpers (B300: 3-reg FFMA is half rate; f32x2 doubles tput)
// ---------------------------------------------------------------------------
__device__ __forceinline__ unsigned long long pk2(float lo, float hi) {
    unsigned long long r;
    asm("mov.b64 %0, {%1, %2};" : "=l"(r) : "f"(lo), "f"(hi));
    return r;
}
__device__ __forceinline__ unsigned long long ffma2(unsigned long long a,
                                                    unsigned long long b,
                                                    unsigned long long c) {
    unsigned long long d;
    asm("fma.rn.f32x2 %0, %1, %2, %3;" : "=l"(d) : "l"(a), "l"(b), "l"(c));
    return d;
}
__device__ __forceinline__ float2 upk2(unsigned long long v) {
    float2 f;
    asm("mov.b64 {%0, %1}, %2;" : "=f"(f.x), "=f"(f.y) : "l"(v));
    return f;
}

// ---------------------------------------------------------------------------
// SGEMM body: C[M,N] = A[M,K] @ B[K,N], row-major, all dims multiples of 128/8.
// 128x128 block tile, BK=8, 256 threads, 8x8 per thread, f32x2 packed FMAs.
// ---------------------------------------------------------------------------
__device__ __forceinline__ void gemm_body(const float* __restrict__ A,
                                          const float* __restrict__ B,
                                          float* __restrict__ C,
                                          int M, int N, int K) {
    __shared__ __align__(16) float As[8][128];
    __shared__ __align__(16) float Bs[8][128];
    const int tid  = threadIdx.x;
    const int bm   = blockIdx.y * 128;
    const int bn   = blockIdx.x * 128;
    const int arow = tid >> 1, acol = (tid & 1) * 4;
    const int brow = tid >> 5, bcol = (tid & 31) * 4;
    const int tm   = (tid >> 4) * 8, tn = (tid & 15) * 8;

    unsigned long long acc[8][4];
#pragma unroll
    for (int i = 0; i < 8; i++)
#pragma unroll
        for (int j = 0; j < 4; j++) acc[i][j] = 0ull;

    const float* Ap = A + (size_t)(bm + arow) * K + acol;
    const float* Bp = B + (size_t)brow * N + bn + bcol;

    for (int k0 = 0; k0 < K; k0 += 8) {
        float4 av = *(const float4*)(Ap + k0);
        float4 bv = *(const float4*)(Bp + (size_t)k0 * N);
        As[acol + 0][arow] = av.x;
        As[acol + 1][arow] = av.y;
        As[acol + 2][arow] = av.z;
        As[acol + 3][arow] = av.w;
        *(float4*)&Bs[brow][bcol] = bv;
        __syncthreads();
#pragma unroll
        for (int kk = 0; kk < 8; kk++) {
            float4 a0 = *(const float4*)&As[kk][tm];
            float4 a1 = *(const float4*)&As[kk][tm + 4];
            float4 b0 = *(const float4*)&Bs[kk][tn];
            float4 b1 = *(const float4*)&Bs[kk][tn + 4];
            unsigned long long B2[4] = {pk2(b0.x, b0.y), pk2(b0.z, b0.w),
                                        pk2(b1.x, b1.y), pk2(b1.z, b1.w)};
            float av8[8] = {a0.x, a0.y, a0.z, a0.w, a1.x, a1.y, a1.z, a1.w};
#pragma unroll
            for (int i = 0; i < 8; i++) {
                unsigned long long a2 = pk2(av8[i], av8[i]);
#pragma unroll
                for (int j = 0; j < 4; j++)
                    acc[i][j] = ffma2(a2, B2[j], acc[i][j]);
            }
        }
        __syncthreads();
    }

#pragma unroll
    for (int i = 0; i < 8; i++) {
        float* crow = C + (size_t)(bm + tm + i) * N + bn + tn;
#pragma unroll
        for (int j = 0; j < 4; j++) {
            float2 f = upk2(acc[i][j]);
            *(float2*)(crow + 2 * j) = f;
        }
    }
}

// 4 projection GEMMs fused via gridDim.z (shared A = x)
__global__ __launch_bounds__(256) void proj_gemm(const float* __restrict__ x,
                                                 const float* __restrict__ Wq,
                                                 const float* __restrict__ Wk,
                                                 const float* __restrict__ Wv,
                                                 const float* __restrict__ Wg) {
    const float* W;
    float* C;
    switch (blockIdx.z) {
        case 0:  W = Wq; C = g_qpre; break;
        case 1:  W = Wk; C = g_kpre; break;
        case 2:  W = Wv; C = g_vpre; break;
        default: W = Wg; C = g_gpre; break;
    }
    gemm_body(x, W, C, BT, DD, DD);
}

__global__ __launch_bounds__(256) void out_gemm(const float* __restrict__ Wo,
                                                float* __restrict__ out) {
    gemm_body(g_og, Wo, out, BT, DD, DD);
}

// ---------------------------------------------------------------------------
// beta = sigmoid(x @ Wb), Wb (1024,16)
// ---------------------------------------------------------------------------
__global__ __launch_bounds__(256) void beta_kernel(const float* __restrict__ x,
                                                   const float* __restrict__ Wb) {
    int row  = blockIdx.x * 16 + (threadIdx.x >> 4);
    int hcol = threadIdx.x & 15;
    const float* xr = x + (size_t)row * DD;
    const float* wb = Wb + hcol;
    float acc = 0.f;
#pragma unroll 8
    for (int kk = 0; kk < DD; kk++) acc = fmaf(xr[kk], wb[kk * 16], acc);
    g_beta[row * HH + hcol] = 1.f / (1.f + expf(-acc));
}

// ---------------------------------------------------------------------------
// Depthwise causal conv(k=4) + bias + silu, then (for q,k) per-head l2norm.
// mode 0: q (l2norm * 1/sqrt(64)); mode 1: k (l2norm); mode 2: v (silu only).
// grid = BT * (H/4), 256 threads = 4 heads of 64 channels.
// ---------------------------------------------------------------------------
__global__ __launch_bounds__(256) void conv_norm(const float* __restrict__ cw,
                                                 const float* __restrict__ cb,
                                                 int mode) {
    const float* pre = (mode == 0) ? g_qpre : (mode == 1) ? g_kpre : g_vpre;
    float* out       = (mode == 0) ? g_qn   : (mode == 1) ? g_kn   : g_vn;
    int blk = blockIdx.x;
    int hq  = blk & 3;
    int bt  = blk >> 2;
    int t   = bt & (TT - 1);
    int b   = bt >> 11;
    int tid = threadIdx.x;
    int hh  = tid >> 6;        // local head (0..3)
    int ch  = hq * 256 + tid;  // channel 0..1023

    float acc = cb[ch];
#pragma unroll
    for (int j = 0; j < 4; j++) {
        int tt = t - 3 + j;
        if (tt >= 0)
            acc = fmaf(pre[(size_t)(b * TT + tt) * DD + ch], cw[ch * 4 + j], acc);
    }
    float y = acc / (1.f + expf(-acc));  // silu

    if (mode < 2) {
        float ss = y * y;
#pragma unroll
        for (int m = 16; m; m >>= 1) ss += __shfl_xor_sync(0xffffffffu, ss, m);
        __shared__ float red[8];
        if ((tid & 31) == 0) red[tid >> 5] = ss;
        __syncthreads();
        float tot = red[hh * 2] + red[hh * 2 + 1];
        float inv = rsqrtf(tot + 1e-6f);
        if (mode == 0) inv *= 0.125f;  // 1/sqrt(64)
        y *= inv;
    }
    out[(size_t)bt * DD + ch] = y;
}

// ---------------------------------------------------------------------------
// Sequential delta-rule scan.
// State columns evolve independently -> split v-dim 4-way: 128 CTAs (b,h,sv).
// Each CTA: 16 columns x 64 rows of S; 256 threads = (g rowgroup 0..15) x
// (vl column 0..15), thread holds rows [4g,4g+4) of column v0+vl in regs.
// Per-step inputs prefetched with double-buffered cp.async (distance 2).
// ---------------------------------------------------------------------------
__device__ __forceinline__ void cpa4(void* smem, const void* g) {
    unsigned sa = (unsigned)__cvta_generic_to_shared(smem);
    asm volatile("cp.async.ca.shared.global [%0], [%1], 4;\n" ::"r"(sa), "l"(g));
}

__global__ __launch_bounds__(256) void scan_kernel() {
    int blk = blockIdx.x;      // 0..127
    int sv  = blk & 3;
    int bh  = blk >> 2;
    int b   = bh >> 4, h = bh & 15;
    int v0  = sv * 16;
    int tid = threadIdx.x;
    int g   = tid & 15;        // row group
    int vl  = tid >> 4;        // 0..15

    __shared__ __align__(16) float buf[2][160];  // [0,64)=k [64,128)=q [128,144)=v [144]=beta

    const size_t base = (size_t)b * TT * DD + h * DH;
    const float* Kp = g_kn + base;
    const float* Qp = g_qn + base;
    const float* Vp = g_vn + base + v0;
    const float* Bp = g_beta + (size_t)b * TT * HH + h;
    float* Op = g_o + base + v0;

    auto issue = [&](int t, int pb) {
        if (tid < 64)        cpa4(&buf[pb][tid],       Kp + (size_t)t * DD + tid);
        else if (tid < 128)  cpa4(&buf[pb][tid],       Qp + (size_t)t * DD + (tid - 64));
        else if (tid < 144)  cpa4(&buf[pb][tid],       Vp + (size_t)t * DD + (tid - 128));
        else if (tid == 144) cpa4(&buf[pb][144],       Bp + (size_t)t * HH);
    };

    issue(0, 0);
    asm volatile("cp.async.commit_group;\n" ::: "memory");
    issue(1, 1);
    asm volatile("cp.async.commit_group;\n" ::: "memory");

    float s0 = 0.f, s1 = 0.f, s2 = 0.f, s3 = 0.f;

    for (int t = 0; t < TT; t++) {
        int pb = t & 1;
        asm volatile("cp.async.wait_group 1;\n" ::: "memory");
        __syncthreads();

        float4 kv = *(const float4*)&buf[pb][g * 4];
        float4 qv = *(const float4*)&buf[pb][64 + g * 4];
        float  vt = buf[pb][128 + vl];
        float  bt = buf[pb][144];

        // p = k_t . S[:,v]  (partial over 4 rows, reduce over 16 rowgroups)
        float p = fmaf(kv.x, s0, fmaf(kv.y, s1, fmaf(kv.z, s2, kv.w * s3)));
        p += __shfl_xor_sync(0xffffffffu, p, 1);
        p += __shfl_xor_sync(0xffffffffu, p, 2);
        p += __shfl_xor_sync(0xffffffffu, p, 4);
        p += __shfl_xor_sync(0xffffffffu, p, 8);

        float err = (vt - p) * bt;
        s0 = fmaf(kv.x, err, s0);
        s1 = fmaf(kv.y, err, s1);
        s2 = fmaf(kv.z, err, s2);
        s3 = fmaf(kv.w, err, s3);

        float o = fmaf(qv.x, s0, fmaf(qv.y, s1, fmaf(qv.z, s2, qv.w * s3)));
        o += __shfl_xor_sync(0xffffffffu, o, 1);
        o += __shfl_xor_sync(0xffffffffu, o, 2);
        o += __shfl_xor_sync(0xffffffffu, o, 4);
        o += __shfl_xor_sync(0xffffffffu, o, 8);
        if (g == 0) Op[(size_t)t * DD + vl] = o;

        __syncthreads();
        if (t + 2 < TT) issue(t + 2, pb);
        asm volatile("cp.async.commit_group;\n" ::: "memory");
    }
}

// ---------------------------------------------------------------------------
// RMSNorm over head_dim + silu gate -> g_og
// ---------------------------------------------------------------------------
__global__ __launch_bounds__(256) void norm_gate(const float* __restrict__ nw) {
    int blk = blockIdx.x;
    int hq  = blk & 3;
    int bt  = blk >> 2;
    int tid = threadIdx.x;
    int hh  = tid >> 6;
    int c   = tid & 63;
    size_t idx = (size_t)bt * DD + hq * 256 + tid;

    float o  = g_o[idx];
    float ss = o * o;
#pragma unroll
    for (int m = 16; m; m >>= 1) ss += __shfl_xor_sync(0xffffffffu, ss, m);
    __shared__ float red[8];
    if ((tid & 31) == 0) red[tid >> 5] = ss;
    __syncthreads();
    float tot = red[hh * 2] + red[hh * 2 + 1];
    float inv = rsqrtf(tot * (1.f / 64.f) + 1e-5f);
    o *= inv * nw[c];
    float gt = g_gpre[idx];
    o *= gt / (1.f + expf(-gt));
    g_og[idx] = o;
}

// ---------------------------------------------------------------------------
// Launch: x Wq Wk Wv Wo Wg Wb cq_w cq_b ck_w ck_b cv_w cv_b nw
// ---------------------------------------------------------------------------
extern "C" void kernel_launch(void* const* d_in, const int* in_sizes, int n_in,
                              void* d_out, int out_size) {
    const float* x    = (const float*)d_in[0];
    const float* Wq   = (const float*)d_in[1];
    const float* Wk   = (const float*)d_in[2];
    const float* Wv   = (const float*)d_in[3];
    const float* Wo   = (const float*)d_in[4];
    const float* Wg   = (const float*)d_in[5];
    const float* Wb   = (const float*)d_in[6];
    const float* cq_w = (const float*)d_in[7];
    const float* cq_b = (const float*)d_in[8];
    const float* ck_w = (const float*)d_in[9];
    const float* ck_b = (const float*)d_in[10];
    const float* cv_w = (const float*)d_in[11];
    const float* cv_b = (const float*)d_in[12];
    const float* nw   = (const float*)d_in[13];
    float* out = (float*)d_out;

    dim3 gproj(DD / 128, BT / 128, 4);
    proj_gemm<<<gproj, 256>>>(x, Wq, Wk, Wv, Wg);
    beta_kernel<<<BT / 16, 256>>>(x, Wb);
    conv_norm<<<BT * 4, 256>>>(cq_w, cq_b, 0);
    conv_norm<<<BT * 4, 256>>>(ck_w, ck_b, 1);
    conv_norm<<<BT * 4, 256>>>(cv_w, cv_b, 2);
    scan_kernel<<<BB * HH * 4, 256>>>();
    norm_gate<<<BT * 4, 256>>>(nw);
    dim3 gout(DD / 128, BT / 128);
    out_gemm<<<gout, 256>>>(Wo, out);
}

// round 12
// speedup vs baseline: 1.5015x; 1.5015x over previous
#include <cuda_runtime.h>
#include <cuda_bf16.h>
#include <cstdint>

// Problem constants
#define BB    2
#define TT    2048
#define DD    1024
#define HH    16
#define DH    64
#define BT    (BB*TT)          // 4096
#define KBIG  3072             // 3 * DD (split-in-K bf16 GEMM)
#define NELE  ((size_t)BT*DD)  // 4,194,304

// ---------------------------------------------------------------------------
// Scratch (no cudaMalloc allowed -> __device__ globals)
// ---------------------------------------------------------------------------
__device__ float g_qpre[NELE];
__device__ float g_kpre[NELE];
__device__ float g_vpre[NELE];
__device__ float g_gpre[NELE];
__device__ float g_qn[NELE];
__device__ float g_kn[NELE];
__device__ float g_vn[NELE];
__device__ float g_o[NELE];
__device__ float g_beta[BT*HH];

// bf16 split operands for tensor-core GEMMs
__device__ __align__(16) __nv_bfloat16 g_Ax[(size_t)BT*KBIG];      // [Ah|Al|Ah] of x
__device__ __align__(16) __nv_bfloat16 g_Ao[(size_t)BT*KBIG];      // [Ah|Al|Ah] of o*gate
__device__ __align__(16) __nv_bfloat16 g_Bw[5][(size_t)DD*KBIG];   // W^T splits: [Bh|Bh|Bl]

// ---------------------------------------------------------------------------
// Small helpers
// ---------------------------------------------------------------------------
__device__ __forceinline__ uint32_t smem_u32(const void* p) {
    uint32_t a;
    asm("{ .reg .u64 t; cvta.to.shared.u64 t, %1; cvt.u32.u64 %0, t; }"
        : "=r"(a) : "l"(p));
    return a;
}
__device__ __forceinline__ unsigned sw128(unsigned o) { return o ^ ((o >> 3) & 0x70); }
__device__ __forceinline__ void cpa16(unsigned dst, const void* src) {
    asm volatile("cp.async.cg.shared.global [%0], [%1], 16;\n" ::"r"(dst), "l"(src));
}
__device__ __forceinline__ void ldsm4(uint32_t* r, uint32_t addr) {
    asm volatile("ldmatrix.sync.aligned.m8n8.x4.shared.b16 {%0,%1,%2,%3}, [%4];"
                 : "=r"(r[0]), "=r"(r[1]), "=r"(r[2]), "=r"(r[3]) : "r"(addr));
}
__device__ __forceinline__ void mma_bf16(float* d, const uint32_t* a, const uint32_t* b) {
    asm volatile(
        "mma.sync.aligned.m16n8k16.row.col.f32.bf16.bf16.f32 "
        "{%0,%1,%2,%3}, {%4,%5,%6,%7}, {%8,%9}, {%0,%1,%2,%3};"
        : "+f"(d[0]), "+f"(d[1]), "+f"(d[2]), "+f"(d[3])
        : "r"(a[0]), "r"(a[1]), "r"(a[2]), "r"(a[3]), "r"(b[0]), "r"(b[1]));
}

// ---------------------------------------------------------------------------
// Split kernels: x -> g_Ax ([hi|lo|hi]),  W -> W^T splits ([hi|hi|lo])
// ---------------------------------------------------------------------------
__global__ __launch_bounds__(256) void split_x(const float* __restrict__ x) {
    int row = blockIdx.x;
    int c0  = threadIdx.x * 4;
    float4 v = *(const float4*)(x + (size_t)row * DD + c0);
    float vv[4] = {v.x, v.y, v.z, v.w};
    size_t b = (size_t)row * KBIG + c0;
#pragma unroll
    for (int j = 0; j < 4; j++) {
        __nv_bfloat16 hi = __float2bfloat16(vv[j]);
        __nv_bfloat16 lo = __float2bfloat16(vv[j] - __bfloat162float(hi));
        g_Ax[b + j]          = hi;
        g_Ax[b + DD + j]     = lo;
        g_Ax[b + 2 * DD + j] = hi;
    }
}

__global__ __launch_bounds__(1024) void split_w(const float* __restrict__ Wq,
                                                const float* __restrict__ Wk,
                                                const float* __restrict__ Wv,
                                                const float* __restrict__ Wg,
                                                const float* __restrict__ Wo) {
    const float* W;
    switch (blockIdx.z) {
        case 0: W = Wq; break;
        case 1: W = Wk; break;
        case 2: W = Wv; break;
        case 3: W = Wg; break;
        default: W = Wo; break;
    }
    __nv_bfloat16* Bt = g_Bw[blockIdx.z];
    __shared__ float tile[32][33];
    int tx = threadIdx.x, ty = threadIdx.y;
    int k = blockIdx.y * 32 + ty, n = blockIdx.x * 32 + tx;
    tile[ty][tx] = W[(size_t)k * DD + n];
    __syncthreads();
    int nn = blockIdx.x * 32 + ty, kk = blockIdx.y * 32 + tx;
    float v = tile[tx][ty];  // = W[kk][nn]
    __nv_bfloat16 hi = __float2bfloat16(v);
    __nv_bfloat16 lo = __float2bfloat16(v - __bfloat162float(hi));
    size_t b = (size_t)nn * KBIG + kk;
    Bt[b]          = hi;
    Bt[b + DD]     = hi;
    Bt[b + 2 * DD] = lo;
}

// ---------------------------------------------------------------------------
// bf16 tensor-core GEMM via mma.sync (portable HMMA path; tcgen05 PTX is
// rejected by this harness's .target sm_103).
// C[M,N] = A[M,KBIG] * Bt[N,KBIG]^T, fp32 out.
// CTA tile 128x128, BK=64, SW128 smem rows, 3-stage cp.async ring.
// 8 warps: warp grid 4(M) x 2(N), warp tile 32x64.
// ---------------------------------------------------------------------------
#define GBM   128
#define GBN   128
#define GBK   64
#define NSTG  3
#define NS    (KBIG/GBK)            // 48
#define STG_A (GBM*128)             // 16384 B
#define STG_B (GBN*128)             // 16384 B
#define STG_BYTES (STG_A + STG_B)   // 32768 B
#define DSM_BYTES (NSTG*STG_BYTES + 1024)

__device__ __forceinline__ void gemm_mma_body(const __nv_bfloat16* __restrict__ A,
                                              const __nv_bfloat16* __restrict__ Bt,
                                              float* __restrict__ C) {
    extern __shared__ char dynsm[];
    const uint32_t smb = (smem_u32(dynsm) + 1023u) & ~1023u;
    const int tid = threadIdx.x;
    const int wid = tid >> 5, lid = tid & 31;
    const int bm = blockIdx.y * GBM;
    const int bn = blockIdx.x * GBN;
    const int wm = (wid & 3) * 32;   // warp M offset in tile
    const int wn = (wid >> 2) * 64;  // warp N offset in tile

    float acc[2][8][4];
#pragma unroll
    for (int i = 0; i < 2; i++)
#pragma unroll
        for (int j = 0; j < 8; j++)
#pragma unroll
            for (int q = 0; q < 4; q++) acc[i][j][q] = 0.f;

    auto load_stage = [&](int st, int slot) {
        unsigned baseA = smb + slot * STG_BYTES;
        unsigned baseB = baseA + STG_A;
        const __nv_bfloat16* Ab = A + (size_t)bm * KBIG + st * GBK;
        const __nv_bfloat16* Bb = Bt + (size_t)bn * KBIG + st * GBK;
#pragma unroll
        for (int c = tid; c < 1024; c += 256) {
            int r = c >> 3, ci = c & 7;
            cpa16(baseA + sw128(r * 128 + ci * 16), Ab + (size_t)r * KBIG + ci * 8);
        }
#pragma unroll
        for (int c = tid; c < 1024; c += 256) {
            int r = c >> 3, ci = c & 7;
            cpa16(baseB + sw128(r * 128 + ci * 16), Bb + (size_t)r * KBIG + ci * 8);
        }
    };

    // ldmatrix lane-address components (within-tile, before k-step offset)
    // A x4: lanes 0-15 -> rows 0-15 (k bytes +0), lanes 16-31 -> rows 0-15 (k bytes +16)
    const int a_row = (lid & 15);
    const int a_kb  = (lid >> 4) * 16;
    // B x4: reg0 [n0-7,k0-7] reg1 [n0-7,k8-15] reg2 [n8-15,k0-7] reg3 [n8-15,k8-15]
    const int b_row = (lid & 7) + (lid >> 4) * 8;
    const int b_kb  = ((lid >> 3) & 1) * 16;

    load_stage(0, 0);
    asm volatile("cp.async.commit_group;\n" ::: "memory");
    load_stage(1, 1);
    asm volatile("cp.async.commit_group;\n" ::: "memory");

    for (int i = 0; i < NS; i++) {
        const int slot = i % NSTG;
        asm volatile("cp.async.wait_group 1;\n" ::: "memory");
        __syncthreads();

        const unsigned baseA = smb + slot * STG_BYTES;
        const unsigned baseB = baseA + STG_A;

#pragma unroll
        for (int ks = 0; ks < 4; ks++) {
            uint32_t af[2][4];
#pragma unroll
            for (int mt = 0; mt < 2; mt++)
                ldsm4(af[mt],
                      baseA + sw128((wm + mt * 16 + a_row) * 128 + ks * 32 + a_kb));
            uint32_t bfr[4][4];
#pragma unroll
            for (int nt = 0; nt < 4; nt++)
                ldsm4(bfr[nt],
                      baseB + sw128((wn + nt * 16 + b_row) * 128 + ks * 32 + b_kb));
#pragma unroll
            for (int mt = 0; mt < 2; mt++)
#pragma unroll
                for (int n8 = 0; n8 < 8; n8++)
                    mma_bf16(acc[mt][n8], af[mt], &bfr[n8 >> 1][(n8 & 1) * 2]);
        }

        __syncthreads();
        if (i + 2 < NS) load_stage(i + 2, (i + 2) % NSTG);
        asm volatile("cp.async.commit_group;\n" ::: "memory");
    }

    // Epilogue: c0,c1 -> (row g, cols tig*2..+1); c2,c3 -> (row g+8)
    const int g   = lid >> 2;
    const int tig = lid & 3;
#pragma unroll
    for (int mt = 0; mt < 2; mt++) {
#pragma unroll
        for (int n8 = 0; n8 < 8; n8++) {
            int row = bm + wm + mt * 16 + g;
            int col = bn + wn + n8 * 8 + tig * 2;
            float2 lo = make_float2(acc[mt][n8][0], acc[mt][n8][1]);
            float2 hi = make_float2(acc[mt][n8][2], acc[mt][n8][3]);
            *(float2*)(C + (size_t)row * DD + col)       = lo;
            *(float2*)(C + (size_t)(row + 8) * DD + col) = hi;
        }
    }
}

__global__ __launch_bounds__(256) void proj_mma() {
    float* C;
    switch (blockIdx.z) {
        case 0:  C = g_qpre; break;
        case 1:  C = g_kpre; break;
        case 2:  C = g_vpre; break;
        default: C = g_gpre; break;
    }
    gemm_mma_body(g_Ax, g_Bw[blockIdx.z], C);
}

__global__ __launch_bounds__(256) void out_mma(float* __restrict__ out) {
    gemm_mma_body(g_Ao, g_Bw[4], out);
}

// ---------------------------------------------------------------------------
// beta = sigmoid(x @ Wb), Wb (1024,16)
// ---------------------------------------------------------------------------
__global__ __launch_bounds__(256) void beta_kernel(const float* __restrict__ x,
                                                   const float* __restrict__ Wb) {
    int row  = blockIdx.x * 16 + (threadIdx.x >> 4);
    int hcol = threadIdx.x & 15;
    const float* xr = x + (size_t)row * DD;
    const float* wb = Wb + hcol;
    float acc = 0.f;
#pragma unroll 8
    for (int kk = 0; kk < DD; kk++) acc = fmaf(xr[kk], wb[kk * 16], acc);
    g_beta[row * HH + hcol] = 1.f / (1.f + expf(-acc));
}

// ---------------------------------------------------------------------------
// Depthwise causal conv(k=4) + bias + silu, then (for q,k) per-head l2norm.
// ---------------------------------------------------------------------------
__global__ __launch_bounds__(256) void conv_norm(const float* __restrict__ cw,
                                                 const float* __restrict__ cb,
                                                 int mode) {
    const float* pre = (mode == 0) ? g_qpre : (mode == 1) ? g_kpre : g_vpre;
    float* out       = (mode == 0) ? g_qn   : (mode == 1) ? g_kn   : g_vn;
    int blk = blockIdx.x;
    int hq  = blk & 3;
    int bt  = blk >> 2;
    int t   = bt & (TT - 1);
    int b   = bt >> 11;
    int tid = threadIdx.x;
    int hh  = tid >> 6;
    int ch  = hq * 256 + tid;

    float acc = cb[ch];
#pragma unroll
    for (int j = 0; j < 4; j++) {
        int tt = t - 3 + j;
        if (tt >= 0)
            acc = fmaf(pre[(size_t)(b * TT + tt) * DD + ch], cw[ch * 4 + j], acc);
    }
    float y = acc / (1.f + expf(-acc));  // silu

    if (mode < 2) {
        float ss = y * y;
#pragma unroll
        for (int m = 16; m; m >>= 1) ss += __shfl_xor_sync(0xffffffffu, ss, m);
        __shared__ float red[8];
        if ((tid & 31) == 0) red[tid >> 5] = ss;
        __syncthreads();
        float tot = red[hh * 2] + red[hh * 2 + 1];
        float inv = rsqrtf(tot + 1e-6f);
        if (mode == 0) inv *= 0.125f;
        y *= inv;
    }
    out[(size_t)bt * DD + ch] = y;
}

// ---------------------------------------------------------------------------
// Sequential delta-rule scan (unchanged from passing R10 kernel)
// ---------------------------------------------------------------------------
__device__ __forceinline__ void cpa4(void* smem, const void* g) {
    unsigned sa = (unsigned)__cvta_generic_to_shared(smem);
    asm volatile("cp.async.ca.shared.global [%0], [%1], 4;\n" ::"r"(sa), "l"(g));
}

__global__ __launch_bounds__(256) void scan_kernel() {
    int blk = blockIdx.x;
    int sv  = blk & 3;
    int bh  = blk >> 2;
    int b   = bh >> 4, h = bh & 15;
    int v0  = sv * 16;
    int tid = threadIdx.x;
    int g   = tid & 15;
    int vl  = tid >> 4;

    __shared__ __align__(16) float buf[2][160];

    const size_t base = (size_t)b * TT * DD + h * DH;
    const float* Kp = g_kn + base;
    const float* Qp = g_qn + base;
    const float* Vp = g_vn + base + v0;
    const float* Bp = g_beta + (size_t)b * TT * HH + h;
    float* Op = g_o + base + v0;

    auto issue = [&](int t, int pb) {
        if (tid < 64)        cpa4(&buf[pb][tid], Kp + (size_t)t * DD + tid);
        else if (tid < 128)  cpa4(&buf[pb][tid], Qp + (size_t)t * DD + (tid - 64));
        else if (tid < 144)  cpa4(&buf[pb][tid], Vp + (size_t)t * DD + (tid - 128));
        else if (tid == 144) cpa4(&buf[pb][144], Bp + (size_t)t * HH);
    };

    issue(0, 0);
    asm volatile("cp.async.commit_group;\n" ::: "memory");
    issue(1, 1);
    asm volatile("cp.async.commit_group;\n" ::: "memory");

    float s0 = 0.f, s1 = 0.f, s2 = 0.f, s3 = 0.f;

    for (int t = 0; t < TT; t++) {
        int pb = t & 1;
        asm volatile("cp.async.wait_group 1;\n" ::: "memory");
        __syncthreads();

        float4 kv = *(const float4*)&buf[pb][g * 4];
        float4 qv = *(const float4*)&buf[pb][64 + g * 4];
        float  vt = buf[pb][128 + vl];
        float  bt = buf[pb][144];

        float p = fmaf(kv.x, s0, fmaf(kv.y, s1, fmaf(kv.z, s2, kv.w * s3)));
        p += __shfl_xor_sync(0xffffffffu, p, 1);
        p += __shfl_xor_sync(0xffffffffu, p, 2);
        p += __shfl_xor_sync(0xffffffffu, p, 4);
        p += __shfl_xor_sync(0xffffffffu, p, 8);

        float err = (vt - p) * bt;
        s0 = fmaf(kv.x, err, s0);
        s1 = fmaf(kv.y, err, s1);
        s2 = fmaf(kv.z, err, s2);
        s3 = fmaf(kv.w, err, s3);

        float o = fmaf(qv.x, s0, fmaf(qv.y, s1, fmaf(qv.z, s2, qv.w * s3)));
        o += __shfl_xor_sync(0xffffffffu, o, 1);
        o += __shfl_xor_sync(0xffffffffu, o, 2);
        o += __shfl_xor_sync(0xffffffffu, o, 4);
        o += __shfl_xor_sync(0xffffffffu, o, 8);
        if (g == 0) Op[(size_t)t * DD + vl] = o;

        __syncthreads();
        if (t + 2 < TT) issue(t + 2, pb);
        asm volatile("cp.async.commit_group;\n" ::: "memory");
    }
}

// ---------------------------------------------------------------------------
// RMSNorm over head_dim + silu gate -> bf16 split rows of g_Ao
// ---------------------------------------------------------------------------
__global__ __launch_bounds__(256) void norm_gate(const float* __restrict__ nw) {
    int blk = blockIdx.x;
    int hq  = blk & 3;
    int bt  = blk >> 2;
    int tid = threadIdx.x;
    int hh  = tid >> 6;
    int c   = tid & 63;
    int ch  = hq * 256 + tid;
    size_t idx = (size_t)bt * DD + ch;

    float o  = g_o[idx];
    float ss = o * o;
#pragma unroll
    for (int m = 16; m; m >>= 1) ss += __shfl_xor_sync(0xffffffffu, ss, m);
    __shared__ float red[8];
    if ((tid & 31) == 0) red[tid >> 5] = ss;
    __syncthreads();
    float tot = red[hh * 2] + red[hh * 2 + 1];
    float inv = rsqrtf(tot * (1.f / 64.f) + 1e-5f);
    o *= inv * nw[c];
    float gt = g_gpre[idx];
    o *= gt / (1.f + expf(-gt));

    __nv_bfloat16 hi = __float2bfloat16(o);
    __nv_bfloat16 lo = __float2bfloat16(o - __bfloat162float(hi));
    size_t b = (size_t)bt * KBIG + ch;
    g_Ao[b]          = hi;
    g_Ao[b + DD]     = lo;
    g_Ao[b + 2 * DD] = hi;
}

// ---------------------------------------------------------------------------
// Launch: x Wq Wk Wv Wo Wg Wb cq_w cq_b ck_w ck_b cv_w cv_b nw
// ---------------------------------------------------------------------------
extern "C" void kernel_launch(void* const* d_in, const int* in_sizes, int n_in,
                              void* d_out, int out_size) {
    const float* x    = (const float*)d_in[0];
    const float* Wq   = (const float*)d_in[1];
    const float* Wk   = (const float*)d_in[2];
    const float* Wv   = (const float*)d_in[3];
    const float* Wo   = (const float*)d_in[4];
    const float* Wg   = (const float*)d_in[5];
    const float* Wb   = (const float*)d_in[6];
    const float* cq_w = (const float*)d_in[7];
    const float* cq_b = (const float*)d_in[8];
    const float* ck_w = (const float*)d_in[9];
    const float* ck_b = (const float*)d_in[10];
    const float* cv_w = (const float*)d_in[11];
    const float* cv_b = (const float*)d_in[12];
    const float* nw   = (const float*)d_in[13];
    float* out = (float*)d_out;

    cudaFuncSetAttribute(proj_mma, cudaFuncAttributeMaxDynamicSharedMemorySize, DSM_BYTES);
    cudaFuncSetAttribute(out_mma,  cudaFuncAttributeMaxDynamicSharedMemorySize, DSM_BYTES);

    split_x<<<BT, 256>>>(x);
    split_w<<<dim3(32, 32, 5), dim3(32, 32)>>>(Wq, Wk, Wv, Wg, Wo);

    proj_mma<<<dim3(DD / GBN, BT / GBM, 4), 256, DSM_BYTES>>>();

    beta_kernel<<<BT / 16, 256>>>(x, Wb);
    conv_norm<<<BT * 4, 256>>>(cq_w, cq_b, 0);
    conv_norm<<<BT * 4, 256>>>(ck_w, ck_b, 1);
    conv_norm<<<BT * 4, 256>>>(cv_w, cv_b, 2);
    scan_kernel<<<BB * HH * 4, 256>>>();
    norm_gate<<<BT * 4, 256>>>(nw);

    out_mma<<<dim3(DD / GBN, BT / GBM), 256, DSM_BYTES>>>(out);
}